// round 15
// baseline (speedup 1.0000x reference)
#include <cuda_runtime.h>
#include <cstdint>

#define NMAX 1000000

// Scratch (__device__ globals; no allocation allowed)
__device__ float4 g_proj[NMAX];    // projd = proj * dinv   (layers 1,2)
__device__ float4 g_agg[NMAX];     // running sum (seeded with projd[self])
__device__ float  g_dinv[NMAX];    // holds DEGREE (consumers apply rsqrtf)
__device__ float2 g_p2[NMAX];      // layer-3 projd (2-wide)
__device__ float2 g_a2[NMAX];      // layer-3 sum

// ---------------------------------------------------------------------------
// degree (vectorized init: 4 nodes/thread)
// ---------------------------------------------------------------------------
__global__ void k_init_deg(int n) {
    int i = (blockIdx.x * blockDim.x + threadIdx.x) * 4;
    if (i + 4 <= n) {
        *reinterpret_cast<float4*>(&g_dinv[i]) = make_float4(1.f, 1.f, 1.f, 1.f);
    } else {
        for (int j = i; j < n; j++) g_dinv[j] = 1.0f;
    }
}

__device__ __forceinline__ void red_deg(int c) {
    asm volatile("red.global.add.f32 [%0], %1;" :: "l"(&g_dinv[c]), "f"(1.0f) : "memory");
}

__global__ void k_count_deg(const int* __restrict__ col, int E) {
    int t = blockIdx.x * blockDim.x + threadIdx.x;
    int base = t * 8;
    if (base + 8 <= E) {
        int4 c0 = __ldcs(reinterpret_cast<const int4*>(col + base));
        int4 c1 = __ldcs(reinterpret_cast<const int4*>(col + base) + 1);
        red_deg(c0.x); red_deg(c0.y); red_deg(c0.z); red_deg(c0.w);
        red_deg(c1.x); red_deg(c1.y); red_deg(c1.z); red_deg(c1.w);
    } else if (base < E) {
        for (int j = base; j < E; j++) red_deg(__ldcs(col + j));
    }
}

// ---------------------------------------------------------------------------
// Layer 1: projd = (x @ W1) * rsqrt(deg).  Warp handles 2 nodes/iter with
// depth-1 software pipelining (4x128B loads in flight per warp, occ 5).
// W in registers, 11-shuffle transpose reduction per node.
// Seeds agg = projd (self-loop term).
// ---------------------------------------------------------------------------
__global__ void __launch_bounds__(256, 5)
k_proj1(const float* __restrict__ x, const float* __restrict__ W1, int n) {
    int lane = threadIdx.x & 31;
    int warp = (blockIdx.x * blockDim.x + threadIdx.x) >> 5;
    int nwarps = (gridDim.x * blockDim.x) >> 5;

    const float4* W = reinterpret_cast<const float4*>(W1);  // W1 row k -> float4
    float4 w0 = W[4 * lane + 0];
    float4 w1 = W[4 * lane + 1];
    float4 w2 = W[4 * lane + 2];
    float4 w3 = W[4 * lane + 3];

    const float4* x4 = reinterpret_cast<const float4*>(x);
    const unsigned FULL = 0xffffffffu;
    const float4 Z = make_float4(0.f, 0.f, 0.f, 0.f);
    int npairs = (n + 1) >> 1;

    int pair = warp;
    if (pair >= npairs) return;

    // prologue loads
    int nodeA = pair * 2, nodeB = nodeA + 1;
    bool hasB = nodeB < n;
    float4 xa = __ldcs(x4 + (size_t)nodeA * 32 + lane);
    float4 xb = hasB ? __ldcs(x4 + (size_t)nodeB * 32 + lane) : Z;

    while (true) {
        // prefetch next pair (keeps 4 loads in flight per warp)
        int nextPair = pair + nwarps;
        float4 nxa = Z, nxb = Z;
        bool hasNext = nextPair < npairs;
        bool nHasB = false;
        if (hasNext) {
            int nA = nextPair * 2, nB = nA + 1;
            nHasB = nB < n;
            nxa = __ldcs(x4 + (size_t)nA * 32 + lane);
            nxb = nHasB ? __ldcs(x4 + (size_t)nB * 32 + lane) : Z;
        }

        float a0 = xa.x * w0.x + xa.y * w1.x + xa.z * w2.x + xa.w * w3.x;
        float a1 = xa.x * w0.y + xa.y * w1.y + xa.z * w2.y + xa.w * w3.y;
        float a2 = xa.x * w0.z + xa.y * w1.z + xa.z * w2.z + xa.w * w3.z;
        float a3 = xa.x * w0.w + xa.y * w1.w + xa.z * w2.w + xa.w * w3.w;
        float b0 = xb.x * w0.x + xb.y * w1.x + xb.z * w2.x + xb.w * w3.x;
        float b1 = xb.x * w0.y + xb.y * w1.y + xb.z * w2.y + xb.w * w3.y;
        float b2 = xb.x * w0.z + xb.y * w1.z + xb.z * w2.z + xb.w * w3.z;
        float b3 = xb.x * w0.w + xb.y * w1.w + xb.z * w2.w + xb.w * w3.w;

        a0 += __shfl_xor_sync(FULL, a0, 16); b0 += __shfl_xor_sync(FULL, b0, 16);
        a1 += __shfl_xor_sync(FULL, a1, 16); b1 += __shfl_xor_sync(FULL, b1, 16);
        a2 += __shfl_xor_sync(FULL, a2, 16); b2 += __shfl_xor_sync(FULL, b2, 16);
        a3 += __shfl_xor_sync(FULL, a3, 16); b3 += __shfl_xor_sync(FULL, b3, 16);
        a0 += __shfl_xor_sync(FULL, a0, 8);  b0 += __shfl_xor_sync(FULL, b0, 8);
        a1 += __shfl_xor_sync(FULL, a1, 8);  b1 += __shfl_xor_sync(FULL, b1, 8);
        a2 += __shfl_xor_sync(FULL, a2, 8);  b2 += __shfl_xor_sync(FULL, b2, 8);
        a3 += __shfl_xor_sync(FULL, a3, 8);  b3 += __shfl_xor_sync(FULL, b3, 8);

        // lane group g = lane>>3 owns output component g
        int g = lane >> 3;
        float va = (g == 0) ? a0 : (g == 1) ? a1 : (g == 2) ? a2 : a3;
        float vb = (g == 0) ? b0 : (g == 1) ? b1 : (g == 2) ? b2 : b3;
        va += __shfl_xor_sync(FULL, va, 4);  vb += __shfl_xor_sync(FULL, vb, 4);
        va += __shfl_xor_sync(FULL, va, 2);  vb += __shfl_xor_sync(FULL, vb, 2);
        va += __shfl_xor_sync(FULL, va, 1);  vb += __shfl_xor_sync(FULL, vb, 1);

        int sub = lane & 7;
        bool isA = (sub == 0);
        bool isB = (sub == 4) && hasB;
        if (isA | isB) {
            int nod  = isA ? nodeA : nodeB;
            float v  = isA ? va : vb;
            float d  = rsqrtf(__ldg(&g_dinv[nod]));
            float pv = v * d;
            reinterpret_cast<float*>(&g_proj[nod])[g] = pv;
            reinterpret_cast<float*>(&g_agg[nod])[g]  = pv;
        }

        if (!hasNext) break;
        pair = nextPair;
        nodeA = pair * 2; nodeB = nodeA + 1;
        hasB = nHasB;
        xa = nxa; xb = nxb;
    }
}

// ---------------------------------------------------------------------------
// Edge scatter (4-wide): sum[c] += projd[r].  8 edges/thread (measured best).
// ---------------------------------------------------------------------------
__device__ __forceinline__ void red4(int r, int c) {
    float4 p = __ldcg(&g_proj[r]);
    asm volatile("red.global.add.v4.f32 [%0], {%1,%2,%3,%4};"
                 :: "l"(&g_agg[c]), "f"(p.x), "f"(p.y), "f"(p.z), "f"(p.w)
                 : "memory");
}

__global__ void k_scatter4(const int* __restrict__ row,
                           const int* __restrict__ col, int E) {
    int t = blockIdx.x * blockDim.x + threadIdx.x;
    int base = t * 8;
    if (base + 8 <= E) {
        int4 r0 = __ldcs(reinterpret_cast<const int4*>(row + base));
        int4 r1 = __ldcs(reinterpret_cast<const int4*>(row + base) + 1);
        int4 c0 = __ldcs(reinterpret_cast<const int4*>(col + base));
        int4 c1 = __ldcs(reinterpret_cast<const int4*>(col + base) + 1);
        red4(r0.x, c0.x); red4(r0.y, c0.y); red4(r0.z, c0.z); red4(r0.w, c0.w);
        red4(r1.x, c1.x); red4(r1.y, c1.y); red4(r1.z, c1.z); red4(r1.w, c1.w);
    } else if (base < E) {
        for (int j = base; j < E; j++) red4(__ldcs(row + j), __ldcs(col + j));
    }
}

// ---------------------------------------------------------------------------
// Layer 2: t = tanh(dinv*sum + b1); projd = (t @ W2) * dinv; reseed sum.
// ---------------------------------------------------------------------------
__global__ void k_proj2(const float* __restrict__ W2,
                        const float* __restrict__ b1, int n) {
    int i = blockIdx.x * blockDim.x + threadIdx.x;
    if (i >= n) return;
    float4 a = g_agg[i];
    float d = rsqrtf(g_dinv[i]);
    float t0 = tanhf(a.x * d + __ldg(&b1[0]));
    float t1 = tanhf(a.y * d + __ldg(&b1[1]));
    float t2 = tanhf(a.z * d + __ldg(&b1[2]));
    float t3 = tanhf(a.w * d + __ldg(&b1[3]));
    float4 p;
    p.x = (t0 * __ldg(&W2[0]) + t1 * __ldg(&W2[4]) + t2 * __ldg(&W2[8])  + t3 * __ldg(&W2[12])) * d;
    p.y = (t0 * __ldg(&W2[1]) + t1 * __ldg(&W2[5]) + t2 * __ldg(&W2[9])  + t3 * __ldg(&W2[13])) * d;
    p.z = (t0 * __ldg(&W2[2]) + t1 * __ldg(&W2[6]) + t2 * __ldg(&W2[10]) + t3 * __ldg(&W2[14])) * d;
    p.w = (t0 * __ldg(&W2[3]) + t1 * __ldg(&W2[7]) + t2 * __ldg(&W2[11]) + t3 * __ldg(&W2[15])) * d;
    g_proj[i] = p;
    g_agg[i]  = p;
}

// ---------------------------------------------------------------------------
// Layer 3: t = tanh(dinv*sum + b2); projd2 = (t @ W3) * dinv (2-wide).
// ---------------------------------------------------------------------------
__global__ void k_proj3(const float* __restrict__ W3,
                        const float* __restrict__ b2, int n) {
    int i = blockIdx.x * blockDim.x + threadIdx.x;
    if (i >= n) return;
    float4 a = g_agg[i];
    float d = rsqrtf(g_dinv[i]);
    float t0 = tanhf(a.x * d + __ldg(&b2[0]));
    float t1 = tanhf(a.y * d + __ldg(&b2[1]));
    float t2 = tanhf(a.z * d + __ldg(&b2[2]));
    float t3 = tanhf(a.w * d + __ldg(&b2[3]));
    float p0 = (t0 * __ldg(&W3[0]) + t1 * __ldg(&W3[2]) + t2 * __ldg(&W3[4]) + t3 * __ldg(&W3[6])) * d;
    float p1 = (t0 * __ldg(&W3[1]) + t1 * __ldg(&W3[3]) + t2 * __ldg(&W3[5]) + t3 * __ldg(&W3[7])) * d;
    float2 pd = make_float2(p0, p1);
    g_p2[i] = pd;
    g_a2[i] = pd;
}

__device__ __forceinline__ void red2(int r, int c) {
    float2 p = __ldcg(&g_p2[r]);
    asm volatile("red.global.add.v2.f32 [%0], {%1,%2};"
                 :: "l"(&g_a2[c]), "f"(p.x), "f"(p.y)
                 : "memory");
}

__global__ void k_scatter2(const int* __restrict__ row,
                           const int* __restrict__ col, int E) {
    int t = blockIdx.x * blockDim.x + threadIdx.x;
    int base = t * 8;
    if (base + 8 <= E) {
        int4 r0 = __ldcs(reinterpret_cast<const int4*>(row + base));
        int4 r1 = __ldcs(reinterpret_cast<const int4*>(row + base) + 1);
        int4 c0 = __ldcs(reinterpret_cast<const int4*>(col + base));
        int4 c1 = __ldcs(reinterpret_cast<const int4*>(col + base) + 1);
        red2(r0.x, c0.x); red2(r0.y, c0.y); red2(r0.z, c0.z); red2(r0.w, c0.w);
        red2(r1.x, c1.x); red2(r1.y, c1.y); red2(r1.z, c1.z); red2(r1.w, c1.w);
    } else if (base < E) {
        for (int j = base; j < E; j++) red2(__ldcs(row + j), __ldcs(col + j));
    }
}

// ---------------------------------------------------------------------------
// Epilogue: h = tanh(dinv*sum + b3); out = h @ Wc + bc.
// d_out: out[N,16] then h[N,2].  Coalesced writes via smem staging.
// ---------------------------------------------------------------------------
__global__ void k_final(const float* __restrict__ Wc,
                        const float* __restrict__ b3,
                        const float* __restrict__ bc,
                        float* __restrict__ out, int n) {
    __shared__ float sh0[256];
    __shared__ float sh1[256];
    int node = blockIdx.x * 256 + threadIdx.x;
    float h0 = 0.f, h1 = 0.f;
    if (node < n) {
        float2 a = g_a2[node];
        float d = rsqrtf(g_dinv[node]);
        h0 = tanhf(a.x * d + __ldg(&b3[0]));
        h1 = tanhf(a.y * d + __ldg(&b3[1]));
        float2* hp = reinterpret_cast<float2*>(out + (size_t)16 * n);
        __stcs(hp + node, make_float2(h0, h1));
    }
    sh0[threadIdx.x] = h0;
    sh1[threadIdx.x] = h1;
    __syncthreads();

    int blockNodes = min(256, n - (int)blockIdx.x * 256);
    if (blockNodes <= 0) return;
    float4* o4 = reinterpret_cast<float4*>(out + (size_t)blockIdx.x * 256 * 16);
    for (int idx = threadIdx.x; idx < blockNodes * 4; idx += 256) {
        int nd = idx >> 2;
        int j  = (idx & 3) * 4;
        float H0 = sh0[nd], H1 = sh1[nd];
        float4 v;
        v.x = H0 * __ldg(&Wc[j + 0]) + H1 * __ldg(&Wc[16 + j + 0]) + __ldg(&bc[j + 0]);
        v.y = H0 * __ldg(&Wc[j + 1]) + H1 * __ldg(&Wc[16 + j + 1]) + __ldg(&bc[j + 1]);
        v.z = H0 * __ldg(&Wc[j + 2]) + H1 * __ldg(&Wc[16 + j + 2]) + __ldg(&bc[j + 2]);
        v.w = H0 * __ldg(&Wc[j + 3]) + H1 * __ldg(&Wc[16 + j + 3]) + __ldg(&bc[j + 3]);
        __stcs(o4 + idx, v);
    }
}

// ---------------------------------------------------------------------------
// Launch
// ---------------------------------------------------------------------------
extern "C" void kernel_launch(void* const* d_in, const int* in_sizes, int n_in,
                              void* d_out, int out_size) {
    const float* x  = (const float*)d_in[0];
    const int*   ei = (const int*)d_in[1];
    const float* W1 = (const float*)d_in[2];
    const float* b1 = (const float*)d_in[3];
    const float* W2 = (const float*)d_in[4];
    const float* b2 = (const float*)d_in[5];
    const float* W3 = (const float*)d_in[6];
    const float* b3 = (const float*)d_in[7];
    const float* Wc = (const float*)d_in[8];
    const float* bc = (const float*)d_in[9];
    float* out = (float*)d_out;

    const int n = in_sizes[0] / 128;
    const int E = in_sizes[1] / 2;
    const int* row = ei;       // source
    const int* col = ei + E;   // target

    const int TB = 256;
    int nodeBlocks = (n + TB - 1) / TB;
    int initBlocks = ((n + 3) / 4 + TB - 1) / TB;
    int edgeBlocks = ((E + 7) / 8 + TB - 1) / TB;
    int projBlocks = 148 * 5;

    // degree
    k_init_deg<<<initBlocks, TB>>>(n);
    k_count_deg<<<edgeBlocks, TB>>>(col, E);

    // layer 1
    k_proj1<<<projBlocks, TB>>>(x, W1, n);
    k_scatter4<<<edgeBlocks, TB>>>(row, col, E);

    // layer 2
    k_proj2<<<nodeBlocks, TB>>>(W2, b1, n);
    k_scatter4<<<edgeBlocks, TB>>>(row, col, E);

    // layer 3
    k_proj3<<<nodeBlocks, TB>>>(W3, b2, n);
    k_scatter2<<<edgeBlocks, TB>>>(row, col, E);

    // classifier epilogue
    k_final<<<nodeBlocks, TB>>>(Wc, b3, bc, out, n);
}

// round 16
// speedup vs baseline: 1.0055x; 1.0055x over previous
#include <cuda_runtime.h>
#include <cstdint>

#define NMAX 1000000

// Scratch (__device__ globals; no allocation allowed)
__device__ float4 g_proj[NMAX];    // projd = proj * dinv   (layers 1,2)
__device__ float4 g_agg[NMAX];     // running sum (seeded with projd[self])
__device__ float  g_dinv[NMAX];    // holds DEGREE (consumers apply rsqrtf)
__device__ float2 g_p2[NMAX];      // layer-3 projd (2-wide)
__device__ float2 g_a2[NMAX];      // layer-3 sum

// ---------------------------------------------------------------------------
// degree (vectorized init: 4 nodes/thread)
// ---------------------------------------------------------------------------
__global__ void k_init_deg(int n) {
    int i = (blockIdx.x * blockDim.x + threadIdx.x) * 4;
    if (i + 4 <= n) {
        *reinterpret_cast<float4*>(&g_dinv[i]) = make_float4(1.f, 1.f, 1.f, 1.f);
    } else {
        for (int j = i; j < n; j++) g_dinv[j] = 1.0f;
    }
}

__device__ __forceinline__ void red_deg(int c) {
    asm volatile("red.global.add.f32 [%0], %1;" :: "l"(&g_dinv[c]), "f"(1.0f) : "memory");
}

__global__ void k_count_deg(const int* __restrict__ col, int E) {
    int t = blockIdx.x * blockDim.x + threadIdx.x;
    int base = t * 8;
    if (base + 8 <= E) {
        int4 c0 = __ldcs(reinterpret_cast<const int4*>(col + base));
        int4 c1 = __ldcs(reinterpret_cast<const int4*>(col + base) + 1);
        red_deg(c0.x); red_deg(c0.y); red_deg(c0.z); red_deg(c0.w);
        red_deg(c1.x); red_deg(c1.y); red_deg(c1.z); red_deg(c1.w);
    } else if (base < E) {
        for (int j = base; j < E; j++) red_deg(__ldcs(col + j));
    }
}

// ---------------------------------------------------------------------------
// Layer 1: projd = (x @ W1) * rsqrt(deg).  Warp handles 2 nodes/iter with
// depth-1 software pipelining (4x128B loads in flight per warp, occ 5).
// W in registers, 11-shuffle transpose reduction per node.
// Seeds agg = projd (self-loop term).
// ---------------------------------------------------------------------------
__global__ void __launch_bounds__(256, 5)
k_proj1(const float* __restrict__ x, const float* __restrict__ W1, int n) {
    int lane = threadIdx.x & 31;
    int warp = (blockIdx.x * blockDim.x + threadIdx.x) >> 5;
    int nwarps = (gridDim.x * blockDim.x) >> 5;

    const float4* W = reinterpret_cast<const float4*>(W1);  // W1 row k -> float4
    float4 w0 = W[4 * lane + 0];
    float4 w1 = W[4 * lane + 1];
    float4 w2 = W[4 * lane + 2];
    float4 w3 = W[4 * lane + 3];

    const float4* x4 = reinterpret_cast<const float4*>(x);
    const unsigned FULL = 0xffffffffu;
    const float4 Z = make_float4(0.f, 0.f, 0.f, 0.f);
    int npairs = (n + 1) >> 1;

    int pair = warp;
    if (pair >= npairs) return;

    // prologue loads
    int nodeA = pair * 2, nodeB = nodeA + 1;
    bool hasB = nodeB < n;
    float4 xa = __ldcs(x4 + (size_t)nodeA * 32 + lane);
    float4 xb = hasB ? __ldcs(x4 + (size_t)nodeB * 32 + lane) : Z;

    while (true) {
        // prefetch next pair (keeps 4 loads in flight per warp)
        int nextPair = pair + nwarps;
        float4 nxa = Z, nxb = Z;
        bool hasNext = nextPair < npairs;
        bool nHasB = false;
        if (hasNext) {
            int nA = nextPair * 2, nB = nA + 1;
            nHasB = nB < n;
            nxa = __ldcs(x4 + (size_t)nA * 32 + lane);
            nxb = nHasB ? __ldcs(x4 + (size_t)nB * 32 + lane) : Z;
        }

        float a0 = xa.x * w0.x + xa.y * w1.x + xa.z * w2.x + xa.w * w3.x;
        float a1 = xa.x * w0.y + xa.y * w1.y + xa.z * w2.y + xa.w * w3.y;
        float a2 = xa.x * w0.z + xa.y * w1.z + xa.z * w2.z + xa.w * w3.z;
        float a3 = xa.x * w0.w + xa.y * w1.w + xa.z * w2.w + xa.w * w3.w;
        float b0 = xb.x * w0.x + xb.y * w1.x + xb.z * w2.x + xb.w * w3.x;
        float b1 = xb.x * w0.y + xb.y * w1.y + xb.z * w2.y + xb.w * w3.y;
        float b2 = xb.x * w0.z + xb.y * w1.z + xb.z * w2.z + xb.w * w3.z;
        float b3 = xb.x * w0.w + xb.y * w1.w + xb.z * w2.w + xb.w * w3.w;

        a0 += __shfl_xor_sync(FULL, a0, 16); b0 += __shfl_xor_sync(FULL, b0, 16);
        a1 += __shfl_xor_sync(FULL, a1, 16); b1 += __shfl_xor_sync(FULL, b1, 16);
        a2 += __shfl_xor_sync(FULL, a2, 16); b2 += __shfl_xor_sync(FULL, b2, 16);
        a3 += __shfl_xor_sync(FULL, a3, 16); b3 += __shfl_xor_sync(FULL, b3, 16);
        a0 += __shfl_xor_sync(FULL, a0, 8);  b0 += __shfl_xor_sync(FULL, b0, 8);
        a1 += __shfl_xor_sync(FULL, a1, 8);  b1 += __shfl_xor_sync(FULL, b1, 8);
        a2 += __shfl_xor_sync(FULL, a2, 8);  b2 += __shfl_xor_sync(FULL, b2, 8);
        a3 += __shfl_xor_sync(FULL, a3, 8);  b3 += __shfl_xor_sync(FULL, b3, 8);

        // lane group g = lane>>3 owns output component g
        int g = lane >> 3;
        float va = (g == 0) ? a0 : (g == 1) ? a1 : (g == 2) ? a2 : a3;
        float vb = (g == 0) ? b0 : (g == 1) ? b1 : (g == 2) ? b2 : b3;
        va += __shfl_xor_sync(FULL, va, 4);  vb += __shfl_xor_sync(FULL, vb, 4);
        va += __shfl_xor_sync(FULL, va, 2);  vb += __shfl_xor_sync(FULL, vb, 2);
        va += __shfl_xor_sync(FULL, va, 1);  vb += __shfl_xor_sync(FULL, vb, 1);

        int sub = lane & 7;
        bool isA = (sub == 0);
        bool isB = (sub == 4) && hasB;
        if (isA | isB) {
            int nod  = isA ? nodeA : nodeB;
            float v  = isA ? va : vb;
            float d  = rsqrtf(__ldg(&g_dinv[nod]));
            float pv = v * d;
            reinterpret_cast<float*>(&g_proj[nod])[g] = pv;
            reinterpret_cast<float*>(&g_agg[nod])[g]  = pv;
        }

        if (!hasNext) break;
        pair = nextPair;
        nodeA = pair * 2; nodeB = nodeA + 1;
        hasB = nHasB;
        xa = nxa; xb = nxb;
    }
}

// ---------------------------------------------------------------------------
// Edge scatter (4-wide): sum[c] += projd[r].  8 edges/thread (measured best).
// ---------------------------------------------------------------------------
__device__ __forceinline__ void red4(int r, int c) {
    float4 p = __ldcg(&g_proj[r]);
    asm volatile("red.global.add.v4.f32 [%0], {%1,%2,%3,%4};"
                 :: "l"(&g_agg[c]), "f"(p.x), "f"(p.y), "f"(p.z), "f"(p.w)
                 : "memory");
}

__global__ void k_scatter4(const int* __restrict__ row,
                           const int* __restrict__ col, int E) {
    int t = blockIdx.x * blockDim.x + threadIdx.x;
    int base = t * 8;
    if (base + 8 <= E) {
        int4 r0 = __ldcs(reinterpret_cast<const int4*>(row + base));
        int4 r1 = __ldcs(reinterpret_cast<const int4*>(row + base) + 1);
        int4 c0 = __ldcs(reinterpret_cast<const int4*>(col + base));
        int4 c1 = __ldcs(reinterpret_cast<const int4*>(col + base) + 1);
        red4(r0.x, c0.x); red4(r0.y, c0.y); red4(r0.z, c0.z); red4(r0.w, c0.w);
        red4(r1.x, c1.x); red4(r1.y, c1.y); red4(r1.z, c1.z); red4(r1.w, c1.w);
    } else if (base < E) {
        for (int j = base; j < E; j++) red4(__ldcs(row + j), __ldcs(col + j));
    }
}

// ---------------------------------------------------------------------------
// Layer 2: t = tanh(dinv*sum + b1); projd = (t @ W2) * dinv; reseed sum.
// ---------------------------------------------------------------------------
__global__ void k_proj2(const float* __restrict__ W2,
                        const float* __restrict__ b1, int n) {
    int i = blockIdx.x * blockDim.x + threadIdx.x;
    if (i >= n) return;
    float4 a = g_agg[i];
    float d = rsqrtf(g_dinv[i]);
    float t0 = tanhf(a.x * d + __ldg(&b1[0]));
    float t1 = tanhf(a.y * d + __ldg(&b1[1]));
    float t2 = tanhf(a.z * d + __ldg(&b1[2]));
    float t3 = tanhf(a.w * d + __ldg(&b1[3]));
    float4 p;
    p.x = (t0 * __ldg(&W2[0]) + t1 * __ldg(&W2[4]) + t2 * __ldg(&W2[8])  + t3 * __ldg(&W2[12])) * d;
    p.y = (t0 * __ldg(&W2[1]) + t1 * __ldg(&W2[5]) + t2 * __ldg(&W2[9])  + t3 * __ldg(&W2[13])) * d;
    p.z = (t0 * __ldg(&W2[2]) + t1 * __ldg(&W2[6]) + t2 * __ldg(&W2[10]) + t3 * __ldg(&W2[14])) * d;
    p.w = (t0 * __ldg(&W2[3]) + t1 * __ldg(&W2[7]) + t2 * __ldg(&W2[11]) + t3 * __ldg(&W2[15])) * d;
    g_proj[i] = p;
    g_agg[i]  = p;
}

// ---------------------------------------------------------------------------
// Layer 3: t = tanh(dinv*sum + b2); projd2 = (t @ W3) * dinv (2-wide).
// ---------------------------------------------------------------------------
__global__ void k_proj3(const float* __restrict__ W3,
                        const float* __restrict__ b2, int n) {
    int i = blockIdx.x * blockDim.x + threadIdx.x;
    if (i >= n) return;
    float4 a = g_agg[i];
    float d = rsqrtf(g_dinv[i]);
    float t0 = tanhf(a.x * d + __ldg(&b2[0]));
    float t1 = tanhf(a.y * d + __ldg(&b2[1]));
    float t2 = tanhf(a.z * d + __ldg(&b2[2]));
    float t3 = tanhf(a.w * d + __ldg(&b2[3]));
    float p0 = (t0 * __ldg(&W3[0]) + t1 * __ldg(&W3[2]) + t2 * __ldg(&W3[4]) + t3 * __ldg(&W3[6])) * d;
    float p1 = (t0 * __ldg(&W3[1]) + t1 * __ldg(&W3[3]) + t2 * __ldg(&W3[5]) + t3 * __ldg(&W3[7])) * d;
    float2 pd = make_float2(p0, p1);
    g_p2[i] = pd;
    g_a2[i] = pd;
}

__device__ __forceinline__ void red2(int r, int c) {
    float2 p = __ldcg(&g_p2[r]);
    asm volatile("red.global.add.v2.f32 [%0], {%1,%2};"
                 :: "l"(&g_a2[c]), "f"(p.x), "f"(p.y)
                 : "memory");
}

__global__ void k_scatter2(const int* __restrict__ row,
                           const int* __restrict__ col, int E) {
    int t = blockIdx.x * blockDim.x + threadIdx.x;
    int base = t * 8;
    if (base + 8 <= E) {
        int4 r0 = __ldcs(reinterpret_cast<const int4*>(row + base));
        int4 r1 = __ldcs(reinterpret_cast<const int4*>(row + base) + 1);
        int4 c0 = __ldcs(reinterpret_cast<const int4*>(col + base));
        int4 c1 = __ldcs(reinterpret_cast<const int4*>(col + base) + 1);
        red2(r0.x, c0.x); red2(r0.y, c0.y); red2(r0.z, c0.z); red2(r0.w, c0.w);
        red2(r1.x, c1.x); red2(r1.y, c1.y); red2(r1.z, c1.z); red2(r1.w, c1.w);
    } else if (base < E) {
        for (int j = base; j < E; j++) red2(__ldcs(row + j), __ldcs(col + j));
    }
}

// ---------------------------------------------------------------------------
// Epilogue: h = tanh(dinv*sum + b3); out = h @ Wc + bc.
// d_out: out[N,16] then h[N,2].  Coalesced writes via smem staging.
// ---------------------------------------------------------------------------
__global__ void k_final(const float* __restrict__ Wc,
                        const float* __restrict__ b3,
                        const float* __restrict__ bc,
                        float* __restrict__ out, int n) {
    __shared__ float sh0[256];
    __shared__ float sh1[256];
    int node = blockIdx.x * 256 + threadIdx.x;
    float h0 = 0.f, h1 = 0.f;
    if (node < n) {
        float2 a = g_a2[node];
        float d = rsqrtf(g_dinv[node]);
        h0 = tanhf(a.x * d + __ldg(&b3[0]));
        h1 = tanhf(a.y * d + __ldg(&b3[1]));
        float2* hp = reinterpret_cast<float2*>(out + (size_t)16 * n);
        __stcs(hp + node, make_float2(h0, h1));
    }
    sh0[threadIdx.x] = h0;
    sh1[threadIdx.x] = h1;
    __syncthreads();

    int blockNodes = min(256, n - (int)blockIdx.x * 256);
    if (blockNodes <= 0) return;
    float4* o4 = reinterpret_cast<float4*>(out + (size_t)blockIdx.x * 256 * 16);
    for (int idx = threadIdx.x; idx < blockNodes * 4; idx += 256) {
        int nd = idx >> 2;
        int j  = (idx & 3) * 4;
        float H0 = sh0[nd], H1 = sh1[nd];
        float4 v;
        v.x = H0 * __ldg(&Wc[j + 0]) + H1 * __ldg(&Wc[16 + j + 0]) + __ldg(&bc[j + 0]);
        v.y = H0 * __ldg(&Wc[j + 1]) + H1 * __ldg(&Wc[16 + j + 1]) + __ldg(&bc[j + 1]);
        v.z = H0 * __ldg(&Wc[j + 2]) + H1 * __ldg(&Wc[16 + j + 2]) + __ldg(&bc[j + 2]);
        v.w = H0 * __ldg(&Wc[j + 3]) + H1 * __ldg(&Wc[16 + j + 3]) + __ldg(&bc[j + 3]);
        __stcs(o4 + idx, v);
    }
}

// ---------------------------------------------------------------------------
// Launch
// ---------------------------------------------------------------------------
extern "C" void kernel_launch(void* const* d_in, const int* in_sizes, int n_in,
                              void* d_out, int out_size) {
    const float* x  = (const float*)d_in[0];
    const int*   ei = (const int*)d_in[1];
    const float* W1 = (const float*)d_in[2];
    const float* b1 = (const float*)d_in[3];
    const float* W2 = (const float*)d_in[4];
    const float* b2 = (const float*)d_in[5];
    const float* W3 = (const float*)d_in[6];
    const float* b3 = (const float*)d_in[7];
    const float* Wc = (const float*)d_in[8];
    const float* bc = (const float*)d_in[9];
    float* out = (float*)d_out;

    const int n = in_sizes[0] / 128;
    const int E = in_sizes[1] / 2;
    const int* row = ei;       // source
    const int* col = ei + E;   // target

    const int TB = 256;
    int nodeBlocks = (n + TB - 1) / TB;
    int initBlocks = ((n + 3) / 4 + TB - 1) / TB;
    int edgeBlocks = ((E + 7) / 8 + TB - 1) / TB;
    int projBlocks = 148 * 5;

    // degree
    k_init_deg<<<initBlocks, TB>>>(n);
    k_count_deg<<<edgeBlocks, TB>>>(col, E);

    // layer 1
    k_proj1<<<projBlocks, TB>>>(x, W1, n);
    k_scatter4<<<edgeBlocks, TB>>>(row, col, E);

    // layer 2
    k_proj2<<<nodeBlocks, TB>>>(W2, b1, n);
    k_scatter4<<<edgeBlocks, TB>>>(row, col, E);

    // layer 3
    k_proj3<<<nodeBlocks, TB>>>(W3, b2, n);
    k_scatter2<<<edgeBlocks, TB>>>(row, col, E);

    // classifier epilogue
    k_final<<<nodeBlocks, TB>>>(Wc, b3, bc, out, n);
}